// round 12
// baseline (speedup 1.0000x reference)
#include <cuda_runtime.h>
#include <cuda_fp16.h>
#include <cstdint>

#define CC 256
#define WW 128
#define HH 64
#define BB 2
#define NCOL (BB*HH)
#define HO 256
#define WO 512
#define NOUT (BB*HO*WO)
#define NROWS 512             // output rows (b,i)

// per-fill transaction bytes per pipeline barrier:
// local 2048 + remote-in 2048 + wsum 128 = 4224 (same protocol as R10)
#define TXB 4224u

__device__ __half g_M[CC*CC];            // center-tap weights fp16, row-major [o][c]
__device__ float  g_upart[2][NCOL*WW];   // per-rank partial u
__device__ float  g_psum[NROWS];
__device__ float  g_psumsq[NROWS];

__device__ __forceinline__ uint32_t smem_u32(const void* p) {
    uint32_t a;
    asm("{ .reg .u64 t; cvta.to.shared.u64 t, %1; cvt.u32.u64 %0, t; }"
        : "=r"(a) : "l"(p));
    return a;
}
__device__ __forceinline__ uint32_t cluster_rank() {
    uint32_t r;
    asm("mov.u32 %0, %%cluster_ctarank;" : "=r"(r));
    return r;
}
__device__ __forceinline__ uint32_t mapa_u32(uint32_t addr, uint32_t rank) {
    uint32_t r;
    asm("mapa.shared::cluster.u32 %0, %1, %2;" : "=r"(r) : "r"(addr), "r"(rank));
    return r;
}
#define ST_ASYNC_U32(addr, val, mbar)                                         \
    asm volatile("st.async.shared::cluster.mbarrier::complete_tx::bytes.u32 " \
                 "[%0], %1, [%2];" :: "r"(addr), "r"(val), "r"(mbar) : "memory")
#define MBAR_INIT(mbar, cnt)                                                  \
    asm volatile("mbarrier.init.shared.b64 [%0], %1;"                         \
                 :: "r"(mbar), "r"((uint32_t)(cnt)) : "memory")
#define MBAR_EXPECT_TX(mbar, bytes)                                           \
    asm volatile("mbarrier.arrive.expect_tx.shared::cta.b64 _, [%0], %1;"     \
                 :: "r"(mbar), "r"((uint32_t)(bytes)) : "memory")
#define MBAR_WAIT(mbar, parity) do {                                          \
    uint32_t _m = (mbar), _p = (parity), _done;                               \
    asm volatile("{ .reg .pred p;\n\t"                                        \
        "mbarrier.try_wait.parity.acquire.cluster.shared::cta.b64 p, [%1], %2;\n\t" \
        "selp.b32 %0, 1, 0, p; }"                                             \
        : "=r"(_done) : "r"(_m), "r"(_p) : "memory");                         \
    if (!_done) {                                                             \
        asm volatile("{ .reg .pred P1;\n\t"                                   \
            "WL_%=:\n\t"                                                      \
            "mbarrier.try_wait.parity.acquire.cluster.shared::cta.b64 P1, [%0], %1, 0x989680;\n\t" \
            "@P1 bra.uni WD_%=;\n\t"                                          \
            "bra.uni WL_%=;\n\t"                                              \
            "WD_%=: }" :: "r"(_m), "r"(_p) : "memory");                       \
    }                                                                         \
} while (0)
#define CLUSTER_SYNC() do {                                                   \
    asm volatile("barrier.cluster.arrive.aligned;" ::: "memory");             \
    asm volatile("barrier.cluster.wait.aligned;"   ::: "memory");             \
} while (0)

// ===========================================================================
__global__ void extract_M_kernel(const float* __restrict__ convw) {
    int i = blockIdx.x * 256 + threadIdx.x;
    g_M[i] = __float2half(convw[i * 9 + 4]);
}

// ===========================================================================
// 2-CTA-cluster HMMA double scan, TWO independent pipelines per cluster.
// 32 CTAs = 16 clusters x 8 columns (pipeline A: cols 0-3, B: cols 4-7).
// Each pipeline's per-step body is the R10 loop body verbatim; the two
// bodies are concatenated so each pipeline's DSMEM flight + mbarrier wakeup
// hides behind the other pipeline's LDSM/MMA issue stream.
#define MMA_ASM(dd, a, b0r, b1r)                                              \
    asm volatile(                                                             \
        "mma.sync.aligned.m16n8k16.row.col.f32.f16.f16.f32 "                  \
        "{%0,%1,%2,%3}, {%4,%5,%6,%7}, {%8,%9}, {%0,%1,%2,%3};"               \
        : "+f"((dd)[0]), "+f"((dd)[1]), "+f"((dd)[2]), "+f"((dd)[3])          \
        : "r"((a)[0]), "r"((a)[1]), "r"((a)[2]), "r"((a)[3]),                 \
          "r"(b0r), "r"(b1r))

#define LDSM_T(L, addr)                                                       \
    asm volatile(                                                             \
        "ldmatrix.sync.aligned.m8n8.x4.trans.shared.b16 {%0,%1,%2,%3}, [%4];" \
        : "=r"((L)[0]), "=r"((L)[1]), "=r"((L)[2]), "=r"((L)[3])              \
        : "r"(addr))

__global__ void __launch_bounds__(256, 1) __cluster_dims__(2, 1, 1)
scnn_hmma_kernel(const float* __restrict__ p2, const float* __restrict__ w1g) {
    __shared__ __align__(128) __half Bbuf[2][2][CC * 8];  // [pipe][buf] 16KB
    __shared__ float wsum[2][2][8][4];                    // [pipe][buf]
    __shared__ __align__(8) unsigned long long mbar[2][2];// [pipe][buf]

    const int tid  = threadIdx.x;
    const int wid  = tid >> 5;
    const int lane = tid & 31;
    const int tg   = lane & 3;
    const int g    = lane >> 2;
    const int col0A = (blockIdx.x >> 1) * 8;
    const int col0B = col0A + 4;
    const int colA  = col0A + tg;
    const int colB  = col0B + tg;
    const int bA = colA >> 6, hA = colA & 63;
    const int bB = colB >> 6, hB = colB & 63;
    const uint32_t rank = cluster_rank();
    const uint32_t peer = rank ^ 1u;

    // ---- A fragments: this CTA's M rows [rank*128 + 16*wid, +16) (shared by both pipes)
    uint32_t A[16][4];
    const int rlo = (int)rank * 128 + 16 * wid + g;
    {
        const uint32_t* Mlo = reinterpret_cast<const uint32_t*>(g_M + rlo * CC);
        const uint32_t* Mhi = reinterpret_cast<const uint32_t*>(g_M + (rlo + 8) * CC);
#pragma unroll
        for (int kt = 0; kt < 16; kt++) {
            A[kt][0] = Mlo[kt * 8 + tg];
            A[kt][1] = Mhi[kt * 8 + tg];
            A[kt][2] = Mlo[kt * 8 + tg + 4];
            A[kt][3] = Mhi[kt * 8 + tg + 4];
        }
    }

    const int ch0 = rlo;
    const int ch1 = rlo + 8;
    const float w1a = w1g[ch0];
    const float w1b = w1g[ch1];

    const float4* xpaA = reinterpret_cast<const float4*>(
        p2 + ((size_t)(bA * CC + ch0) * HH + hA) * WW);
    const float4* xpbA = reinterpret_cast<const float4*>(
        p2 + ((size_t)(bA * CC + ch1) * HH + hA) * WW);
    const float4* xpaB = reinterpret_cast<const float4*>(
        p2 + ((size_t)(bB * CC + ch0) * HH + hB) * WW);
    const float4* xpbB = reinterpret_cast<const float4*>(
        p2 + ((size_t)(bB * CC + ch1) * HH + hB) * WW);

    const uint32_t bA32   = smem_u32(&Bbuf[0][0][0]);
    const uint32_t bB32   = smem_u32(&Bbuf[1][0][0]);
    const uint32_t wsA32  = smem_u32(&wsum[0][0][0][0]);
    const uint32_t wsB32  = smem_u32(&wsum[1][0][0][0]);
    const uint32_t barA32 = smem_u32(&mbar[0][0]);
    const uint32_t barB32 = smem_u32(&mbar[1][0]);
    const uint32_t bA32r   = mapa_u32(bA32,  peer);
    const uint32_t bB32r   = mapa_u32(bB32,  peer);
    const uint32_t barA32r = mapa_u32(barA32, peer);
    const uint32_t barB32r = mapa_u32(barB32, peer);
    const uint32_t lmA = bA32 + (uint32_t)lane * 16u;
    const uint32_t lmB = bB32 + (uint32_t)lane * 16u;
    const uint32_t bo0 = (uint32_t)(ch0 * 16 + tg * 4);
    const uint32_t bo1 = (uint32_t)(ch1 * 16 + tg * 4);

    if (tid == 0) {
        MBAR_INIT(barA32, 1);     MBAR_INIT(barA32 + 8, 1);
        MBAR_INIT(barB32, 1);     MBAR_INIT(barB32 + 8, 1);
    }
    __syncthreads();
    CLUSTER_SYNC();
    if (tid == 0) {
        MBAR_EXPECT_TX(barA32,     TXB);
        MBAR_EXPECT_TX(barA32 + 8, TXB);
        MBAR_EXPECT_TX(barB32,     TXB);
        MBAR_EXPECT_TX(barB32 + 8, TXB);
    }

    // ---- step 0 for both pipelines
    float4 curaA = xpaA[0], curbA = xpbA[0];
    float4 curaB = xpaB[0], curbB = xpbB[0];
    float4 nxtaA, nxtbA, nxtaB, nxtbB;
    {
        float usum = w1a * curaA.x + w1b * curbA.x;
        usum += __shfl_xor_sync(0xffffffffu, usum, 4);
        usum += __shfl_xor_sync(0xffffffffu, usum, 8);
        usum += __shfl_xor_sync(0xffffffffu, usum, 16);
        __half2 v0h = __halves2half2(__float2half_rn(curaA.x), __float2half_rn(curaA.x));
        __half2 v1h = __halves2half2(__float2half_rn(curbA.x), __float2half_rn(curbA.x));
        uint32_t v0 = *reinterpret_cast<uint32_t*>(&v0h);
        uint32_t v1 = *reinterpret_cast<uint32_t*>(&v1h);
        ST_ASYNC_U32(bA32  + bo0, v0, barA32);
        ST_ASYNC_U32(bA32  + bo1, v1, barA32);
        ST_ASYNC_U32(bA32r + bo0, v0, barA32r);
        ST_ASYNC_U32(bA32r + bo1, v1, barA32r);
        if (lane < 4)
            ST_ASYNC_U32(wsA32 + (uint32_t)((wid * 4 + lane) * 4),
                         __float_as_uint(usum), barA32);
    }
    {
        float usum = w1a * curaB.x + w1b * curbB.x;
        usum += __shfl_xor_sync(0xffffffffu, usum, 4);
        usum += __shfl_xor_sync(0xffffffffu, usum, 8);
        usum += __shfl_xor_sync(0xffffffffu, usum, 16);
        __half2 v0h = __halves2half2(__float2half_rn(curaB.x), __float2half_rn(curaB.x));
        __half2 v1h = __halves2half2(__float2half_rn(curbB.x), __float2half_rn(curbB.x));
        uint32_t v0 = *reinterpret_cast<uint32_t*>(&v0h);
        uint32_t v1 = *reinterpret_cast<uint32_t*>(&v1h);
        ST_ASYNC_U32(bB32  + bo0, v0, barB32);
        ST_ASYNC_U32(bB32  + bo1, v1, barB32);
        ST_ASYNC_U32(bB32r + bo0, v0, barB32r);
        ST_ASYNC_U32(bB32r + bo1, v1, barB32r);
        if (lane < 4)
            ST_ASYNC_U32(wsB32 + (uint32_t)((wid * 4 + lane) * 4),
                         __float_as_uint(usum), barB32);
    }

    for (int w = 1; w < WW; w++) {
        const int rb = (w - 1) & 1;
        const int wb = rb ^ 1;
        const int j = (w - 1) & 3;
        const uint32_t parity = (uint32_t)(((w - 1) >> 1) & 1);

        // ================= pipeline A (R10 body verbatim) =================
        {
            const uint32_t barL = barA32 + (uint32_t)rb * 8u;
            MBAR_WAIT(barL, parity);
            if (tid == 0 && w <= 125) MBAR_EXPECT_TX(barL, TXB);

            if (tid < 4) {
                float s = 0.f;
#pragma unroll
                for (int q8 = 0; q8 < 8; q8++) s += wsum[0][rb][q8][tid];
                g_upart[rank][(col0A + tid) * WW + (WW - w)] = s;
            }

            const uint32_t base = lmA + (uint32_t)rb * (CC * 8 * 2);
            uint32_t L[8][4];
#pragma unroll
            for (int m8 = 0; m8 < 8; m8++)
                LDSM_T(L[m8], base + (uint32_t)m8 * 512u);

            if (j == 0 && w + 4 <= WW) {
                nxtaA = xpaA[(w + 3) >> 2];
                nxtbA = xpbA[(w + 3) >> 2];
            }

            float d[4] = {0.f, 0.f, 0.f, 0.f};
            float e[4] = {0.f, 0.f, 0.f, 0.f};
#pragma unroll
            for (int m8 = 0; m8 < 8; m8++) {
                MMA_ASM(d, A[2 * m8],     L[m8][0], L[m8][1]);
                MMA_ASM(e, A[2 * m8 + 1], L[m8][2], L[m8][3]);
            }

            float xa = (j == 0) ? curaA.y : (j == 1) ? curaA.z : (j == 2) ? curaA.w : nxtaA.x;
            float xb = (j == 0) ? curbA.y : (j == 1) ? curbA.z : (j == 2) ? curbA.w : nxtbA.x;

            float s1a = xa + fmaxf(d[0] + e[0], 0.f);
            float s2a = s1a + fmaxf(d[1] + e[1], 0.f);
            float s1b = xb + fmaxf(d[2] + e[2], 0.f);
            float s2b = s1b + fmaxf(d[3] + e[3], 0.f);

            float usum = w1a * s2a + w1b * s2b;
            usum += __shfl_xor_sync(0xffffffffu, usum, 4);
            usum += __shfl_xor_sync(0xffffffffu, usum, 8);
            usum += __shfl_xor_sync(0xffffffffu, usum, 16);

            if (w < WW - 1) {
                const uint32_t barWb  = barA32  + (uint32_t)wb * 8u;
                const uint32_t barWbR = barA32r + (uint32_t)wb * 8u;
                const uint32_t bufOff = (uint32_t)wb * (CC * 8 * 2);
                __half2 v0h = __floats2half2_rn(s1a, s2a);
                __half2 v1h = __floats2half2_rn(s1b, s2b);
                uint32_t v0 = *reinterpret_cast<uint32_t*>(&v0h);
                uint32_t v1 = *reinterpret_cast<uint32_t*>(&v1h);
                ST_ASYNC_U32(bA32  + bufOff + bo0, v0, barWb);
                ST_ASYNC_U32(bA32  + bufOff + bo1, v1, barWb);
                ST_ASYNC_U32(bA32r + bufOff + bo0, v0, barWbR);
                ST_ASYNC_U32(bA32r + bufOff + bo1, v1, barWbR);
                if (lane < 4)
                    ST_ASYNC_U32(wsA32 + (uint32_t)(((wb * 8 + wid) * 4 + lane) * 4),
                                 __float_as_uint(usum), barWb);
            } else {
                if (lane < 4) wsum[0][1][wid][lane] = usum;
            }

            if (j == 3) { curaA = nxtaA; curbA = nxtbA; }
        }

        // ================= pipeline B (identical, own buffers) =============
        {
            const uint32_t barL = barB32 + (uint32_t)rb * 8u;
            MBAR_WAIT(barL, parity);
            if (tid == 0 && w <= 125) MBAR_EXPECT_TX(barL, TXB);

            if (tid < 4) {
                float s = 0.f;
#pragma unroll
                for (int q8 = 0; q8 < 8; q8++) s += wsum[1][rb][q8][tid];
                g_upart[rank][(col0B + tid) * WW + (WW - w)] = s;
            }

            const uint32_t base = lmB + (uint32_t)rb * (CC * 8 * 2);
            uint32_t L[8][4];
#pragma unroll
            for (int m8 = 0; m8 < 8; m8++)
                LDSM_T(L[m8], base + (uint32_t)m8 * 512u);

            if (j == 0 && w + 4 <= WW) {
                nxtaB = xpaB[(w + 3) >> 2];
                nxtbB = xpbB[(w + 3) >> 2];
            }

            float d[4] = {0.f, 0.f, 0.f, 0.f};
            float e[4] = {0.f, 0.f, 0.f, 0.f};
#pragma unroll
            for (int m8 = 0; m8 < 8; m8++) {
                MMA_ASM(d, A[2 * m8],     L[m8][0], L[m8][1]);
                MMA_ASM(e, A[2 * m8 + 1], L[m8][2], L[m8][3]);
            }

            float xa = (j == 0) ? curaB.y : (j == 1) ? curaB.z : (j == 2) ? curaB.w : nxtaB.x;
            float xb = (j == 0) ? curbB.y : (j == 1) ? curbB.z : (j == 2) ? curbB.w : nxtbB.x;

            float s1a = xa + fmaxf(d[0] + e[0], 0.f);
            float s2a = s1a + fmaxf(d[1] + e[1], 0.f);
            float s1b = xb + fmaxf(d[2] + e[2], 0.f);
            float s2b = s1b + fmaxf(d[3] + e[3], 0.f);

            float usum = w1a * s2a + w1b * s2b;
            usum += __shfl_xor_sync(0xffffffffu, usum, 4);
            usum += __shfl_xor_sync(0xffffffffu, usum, 8);
            usum += __shfl_xor_sync(0xffffffffu, usum, 16);

            if (w < WW - 1) {
                const uint32_t barWb  = barB32  + (uint32_t)wb * 8u;
                const uint32_t barWbR = barB32r + (uint32_t)wb * 8u;
                const uint32_t bufOff = (uint32_t)wb * (CC * 8 * 2);
                __half2 v0h = __floats2half2_rn(s1a, s2a);
                __half2 v1h = __floats2half2_rn(s1b, s2b);
                uint32_t v0 = *reinterpret_cast<uint32_t*>(&v0h);
                uint32_t v1 = *reinterpret_cast<uint32_t*>(&v1h);
                ST_ASYNC_U32(bB32  + bufOff + bo0, v0, barWb);
                ST_ASYNC_U32(bB32  + bufOff + bo1, v1, barWb);
                ST_ASYNC_U32(bB32r + bufOff + bo0, v0, barWbR);
                ST_ASYNC_U32(bB32r + bufOff + bo1, v1, barWbR);
                if (lane < 4)
                    ST_ASYNC_U32(wsB32 + (uint32_t)(((wb * 8 + wid) * 4 + lane) * 4),
                                 __float_as_uint(usum), barWb);
            } else {
                if (lane < 4) wsum[1][1][wid][lane] = usum;
            }

            if (j == 3) { curaB = nxtaB; curbB = nxtbB; }
        }
    }

    __syncthreads();
    if (tid < 4) {
        float sA = 0.f, sB = 0.f;
#pragma unroll
        for (int q8 = 0; q8 < 8; q8++) {
            sA += wsum[0][1][q8][tid];
            sB += wsum[1][1][q8][tid];
        }
        g_upart[rank][(col0A + tid) * WW + 0] = sA;
        g_upart[rank][(col0B + tid) * WW + 0] = sB;
    }
    CLUSTER_SYNC();
}

// ===========================================================================
__device__ __forceinline__ void stage_rows(float* su0, float* su1,
                                           int b, int i, float& wy) {
    float ys = (float)i * (63.0f / 255.0f);
    int y0 = (int)ys;
    wy = ys - (float)y0;
    int y1 = min(y0 + 1, HH - 1);
    int t = threadIdx.x;
    if (t < 128)
        su0[t] = g_upart[0][(b * HH + y0) * WW + t]
               + g_upart[1][(b * HH + y0) * WW + t];
    else if (t < 256)
        su1[t - 128] = g_upart[0][(b * HH + y1) * WW + (t - 128)]
                     + g_upart[1][(b * HH + y1) * WW + (t - 128)];
}

__device__ __forceinline__ float bilin(const float* su0, const float* su1,
                                       int j, float wy) {
    float xs = (float)j * (127.0f / 511.0f);
    int x0 = (int)xs;
    float wx = xs - (float)x0;
    int x1 = min(x0 + 1, WW - 1);
    float r0 = su0[x0] * (1.f - wy) + su1[x0] * wy;
    float r1 = su0[x1] * (1.f - wy) + su1[x1] * wy;
    return r0 * (1.f - wx) + r1 * wx;
}

__global__ void stats_kernel() {
    __shared__ float su0[128], su1[128];
    __shared__ float rs[8], rq[8];
    int row = blockIdx.x;
    int b = row >> 8, i = row & 255;
    float wy;
    stage_rows(su0, su1, b, i, wy);
    __syncthreads();

    int t = threadIdx.x;
    float sum = 0.f, sq = 0.f;
#pragma unroll
    for (int rr = 0; rr < 2; rr++) {
        float v = bilin(su0, su1, t + rr * 256, wy);
        sum += v;
        sq  += v * v;
    }
#pragma unroll
    for (int o = 16; o; o >>= 1) {
        sum += __shfl_xor_sync(0xffffffffu, sum, o);
        sq  += __shfl_xor_sync(0xffffffffu, sq,  o);
    }
    if ((t & 31) == 0) { rs[t >> 5] = sum; rq[t >> 5] = sq; }
    __syncthreads();
    if (t == 0) {
        float a = 0.f, c = 0.f;
#pragma unroll
        for (int k = 0; k < 8; k++) { a += rs[k]; c += rq[k]; }
        g_psum[row] = a; g_psumsq[row] = c;
    }
}

__global__ void output_kernel(float* __restrict__ out,
                              const float* __restrict__ gamma,
                              const float* __restrict__ beta) {
    __shared__ float su0[128], su1[128];
    __shared__ float rs[8], rq[8];
    __shared__ float stats2[2];
    int row = blockIdx.x;
    int b = row >> 8, i = row & 255;
    float wy;
    stage_rows(su0, su1, b, i, wy);

    int t = threadIdx.x;
    float sum = g_psum[t] + g_psum[t + 256];
    float sq  = g_psumsq[t] + g_psumsq[t + 256];
#pragma unroll
    for (int o = 16; o; o >>= 1) {
        sum += __shfl_xor_sync(0xffffffffu, sum, o);
        sq  += __shfl_xor_sync(0xffffffffu, sq,  o);
    }
    if ((t & 31) == 0) { rs[t >> 5] = sum; rq[t >> 5] = sq; }
    __syncthreads();
    if (t == 0) {
        float a = 0.f, c = 0.f;
#pragma unroll
        for (int k = 0; k < 8; k++) { a += rs[k]; c += rq[k]; }
        float inv_n = 1.0f / (float)NOUT;
        float mean  = a * inv_n;
        float var   = c * inv_n - mean * mean;
        stats2[0] = mean;
        stats2[1] = rsqrtf(var + 1e-5f);
    }
    __syncthreads();

    float mean = stats2[0], istd = stats2[1];
    float gm = gamma[0], bt = beta[0];
#pragma unroll
    for (int rr = 0; rr < 2; rr++) {
        int j = t + rr * 256;
        float v = bilin(su0, su1, j, wy);
        float y = (v - mean) * istd * gm + bt;
        out[row * WO + j] = 1.0f / (1.0f + expf(-y));
    }
}

// ===========================================================================
extern "C" void kernel_launch(void* const* d_in, const int* in_sizes, int n_in,
                              void* d_out, int out_size) {
    const float* p2    = (const float*)d_in[0];
    const float* convw = (const float*)d_in[1];
    const float* conv1 = (const float*)d_in[2];
    const float* gamma = (const float*)d_in[3];
    const float* beta  = (const float*)d_in[4];
    float* out = (float*)d_out;

    extract_M_kernel<<<256, 256>>>(convw);
    scnn_hmma_kernel<<<32, 256>>>(p2, conv1);
    stats_kernel<<<NROWS, 256>>>();
    output_kernel<<<NROWS, 256>>>(out, gamma, beta);
}

// round 13
// speedup vs baseline: 1.4504x; 1.4504x over previous
#include <cuda_runtime.h>
#include <cuda_fp16.h>
#include <cstdint>

#define CC 256
#define WW 128
#define HH 64
#define BB 2
#define NCOL (BB*HH)
#define HO 256
#define WO 512
#define NOUT (BB*HO*WO)
#define NROWS 512             // output rows (b,i)

// per-fill transaction bytes: local 2048 + remote 2048 + wsum 128
#define TXB 4224u

__device__ float  g_upart[2][NCOL*WW];   // per-rank partial u
__device__ float  g_psum[NROWS];
__device__ float  g_psumsq[NROWS];

__device__ __forceinline__ uint32_t smem_u32(const void* p) {
    uint32_t a;
    asm("{ .reg .u64 t; cvta.to.shared.u64 t, %1; cvt.u32.u64 %0, t; }"
        : "=r"(a) : "l"(p));
    return a;
}
__device__ __forceinline__ uint32_t cluster_rank() {
    uint32_t r;
    asm("mov.u32 %0, %%cluster_ctarank;" : "=r"(r));
    return r;
}
__device__ __forceinline__ uint32_t mapa_u32(uint32_t addr, uint32_t rank) {
    uint32_t r;
    asm("mapa.shared::cluster.u32 %0, %1, %2;" : "=r"(r) : "r"(addr), "r"(rank));
    return r;
}
#define ST_ASYNC_U32(addr, val, mbar)                                         \
    asm volatile("st.async.shared::cluster.mbarrier::complete_tx::bytes.u32 " \
                 "[%0], %1, [%2];" :: "r"(addr), "r"(val), "r"(mbar) : "memory")
#define MBAR_INIT(mbar, cnt)                                                  \
    asm volatile("mbarrier.init.shared.b64 [%0], %1;"                         \
                 :: "r"(mbar), "r"((uint32_t)(cnt)) : "memory")
#define MBAR_EXPECT_TX(mbar, bytes)                                           \
    asm volatile("mbarrier.arrive.expect_tx.shared::cta.b64 _, [%0], %1;"     \
                 :: "r"(mbar), "r"((uint32_t)(bytes)) : "memory")
#define MBAR_WAIT(mbar, parity) do {                                          \
    uint32_t _m = (mbar), _p = (parity), _done;                               \
    asm volatile("{ .reg .pred p;\n\t"                                        \
        "mbarrier.try_wait.parity.acquire.cluster.shared::cta.b64 p, [%1], %2;\n\t" \
        "selp.b32 %0, 1, 0, p; }"                                             \
        : "=r"(_done) : "r"(_m), "r"(_p) : "memory");                         \
    if (!_done) {                                                             \
        asm volatile("{ .reg .pred P1;\n\t"                                   \
            "WL_%=:\n\t"                                                      \
            "mbarrier.try_wait.parity.acquire.cluster.shared::cta.b64 P1, [%0], %1, 0x989680;\n\t" \
            "@P1 bra.uni WD_%=;\n\t"                                          \
            "bra.uni WL_%=;\n\t"                                              \
            "WD_%=: }" :: "r"(_m), "r"(_p) : "memory");                       \
    }                                                                         \
} while (0)
#define CLUSTER_SYNC() do {                                                   \
    asm volatile("barrier.cluster.arrive.aligned;" ::: "memory");             \
    asm volatile("barrier.cluster.wait.aligned;"   ::: "memory");             \
} while (0)

// ===========================================================================
// 2-CTA-cluster HMMA double scan (R10 structure, schedule-preserving tweaks).
// 64 CTAs = 32 clusters x 4 columns. Each CTA computes 128 output channels
// (16 MMAs/warp/step). Per step each CTA writes its half of the new S into
// BOTH CTAs' B buffers via st.async (tx-counted); one mbarrier per buffer
// parity, count=1 (tid0 expect_tx re-arm) + TXB bytes.
// Deltas vs R10: x prefetch hoisted above the wait; B st.asyncs issued before
// the usum shfl chain; A fragments loaded directly from conv_w (no extract
// kernel).
#define MMA_ASM(dd, a, b0r, b1r)                                              \
    asm volatile(                                                             \
        "mma.sync.aligned.m16n8k16.row.col.f32.f16.f16.f32 "                  \
        "{%0,%1,%2,%3}, {%4,%5,%6,%7}, {%8,%9}, {%0,%1,%2,%3};"               \
        : "+f"((dd)[0]), "+f"((dd)[1]), "+f"((dd)[2]), "+f"((dd)[3])          \
        : "r"((a)[0]), "r"((a)[1]), "r"((a)[2]), "r"((a)[3]),                 \
          "r"(b0r), "r"(b1r))

#define LDSM_T(L, addr)                                                       \
    asm volatile(                                                             \
        "ldmatrix.sync.aligned.m8n8.x4.trans.shared.b16 {%0,%1,%2,%3}, [%4];" \
        : "=r"((L)[0]), "=r"((L)[1]), "=r"((L)[2]), "=r"((L)[3])              \
        : "r"(addr))

__global__ void __launch_bounds__(256, 1) __cluster_dims__(2, 1, 1)
scnn_hmma_kernel(const float* __restrict__ p2, const float* __restrict__ convw,
                 const float* __restrict__ w1g) {
    __shared__ __align__(128) __half Bbuf[2][CC * 8];   // [buf][k*8 + n] 2x4KB
    __shared__ float wsum[2][8][4];
    __shared__ __align__(8) unsigned long long mbar[2];

    const int tid  = threadIdx.x;
    const int wid  = tid >> 5;
    const int lane = tid & 31;
    const int tg   = lane & 3;
    const int g    = lane >> 2;
    const int col0 = (blockIdx.x >> 1) * 4;
    const int col  = col0 + tg;
    const int b    = col >> 6;
    const int h    = col & 63;
    const uint32_t rank = cluster_rank();
    const uint32_t peer = rank ^ 1u;

    // ---- A fragments straight from conv_w center tap (stride-9 gather)
    uint32_t A[16][4];
    const int rlo = (int)rank * 128 + 16 * wid + g;
    {
        const int base_lo = rlo * CC;
        const int base_hi = (rlo + 8) * CC;
#pragma unroll
        for (int kt = 0; kt < 16; kt++) {
            int c0 = kt * 16 + tg * 2;
#pragma unroll
            for (int q = 0; q < 4; q++) {
                int row_base = (q & 1) ? base_hi : base_lo;
                int cc = c0 + ((q >> 1) ? 8 : 0);
                float f0 = convw[(row_base + cc)     * 9 + 4];
                float f1 = convw[(row_base + cc + 1) * 9 + 4];
                __half2 hh = __floats2half2_rn(f0, f1);
                A[kt][q] = *reinterpret_cast<uint32_t*>(&hh);
            }
        }
    }

    const int ch0 = rlo;
    const int ch1 = rlo + 8;
    const float w1a = w1g[ch0];
    const float w1b = w1g[ch1];

    const float4* xpa = reinterpret_cast<const float4*>(
        p2 + ((size_t)(b * CC + ch0) * HH + h) * WW);
    const float4* xpb = reinterpret_cast<const float4*>(
        p2 + ((size_t)(b * CC + ch1) * HH + h) * WW);

    const uint32_t b32    = smem_u32(&Bbuf[0][0]);
    const uint32_t ws32   = smem_u32(&wsum[0][0][0]);
    const uint32_t bar32  = smem_u32(&mbar[0]);
    const uint32_t b32r   = mapa_u32(b32,  peer);
    const uint32_t bar32r = mapa_u32(bar32, peer);
    const uint32_t lmaddr = b32 + (uint32_t)lane * 16u;
    const uint32_t bo0 = (uint32_t)(ch0 * 16 + tg * 4);
    const uint32_t bo1 = (uint32_t)(ch1 * 16 + tg * 4);

    if (tid == 0) { MBAR_INIT(bar32, 1); MBAR_INIT(bar32 + 8, 1); }
    __syncthreads();
    CLUSTER_SYNC();
    if (tid == 0) {
        MBAR_EXPECT_TX(bar32,     TXB);   // fill 0 of buffer 0 (step 0)
        MBAR_EXPECT_TX(bar32 + 8, TXB);   // fill 0 of buffer 1 (step 1)
    }

    // ---- step 0: s1[0] = s2[0] = x[:,0]  -> buffer 0 (both CTAs)
    float4 cura = xpa[0], curb = xpb[0];
    float4 nxta, nxtb;
    {
        __half2 v0h = __halves2half2(__float2half_rn(cura.x), __float2half_rn(cura.x));
        __half2 v1h = __halves2half2(__float2half_rn(curb.x), __float2half_rn(curb.x));
        uint32_t v0 = *reinterpret_cast<uint32_t*>(&v0h);
        uint32_t v1 = *reinterpret_cast<uint32_t*>(&v1h);
        ST_ASYNC_U32(b32  + bo0, v0, bar32);
        ST_ASYNC_U32(b32  + bo1, v1, bar32);
        ST_ASYNC_U32(b32r + bo0, v0, bar32r);
        ST_ASYNC_U32(b32r + bo1, v1, bar32r);

        float usum = w1a * cura.x + w1b * curb.x;
        usum += __shfl_xor_sync(0xffffffffu, usum, 4);
        usum += __shfl_xor_sync(0xffffffffu, usum, 8);
        usum += __shfl_xor_sync(0xffffffffu, usum, 16);
        if (lane < 4)
            ST_ASYNC_U32(ws32 + (uint32_t)((wid * 4 + lane) * 4),
                         __float_as_uint(usum), bar32);
    }

    for (int w = 1; w < WW; w++) {
        const int rb = (w - 1) & 1;
        const int wb = rb ^ 1;
        const int j = (w - 1) & 3;

        // prefetch next float4 group BEFORE the wait (barrier-independent)
        if (j == 0 && w + 4 <= WW) {
            nxta = xpa[(w + 3) >> 2];
            nxtb = xpb[(w + 3) >> 2];
        }

        const uint32_t barL = bar32 + (uint32_t)rb * 8u;
        MBAR_WAIT(barL, (uint32_t)(((w - 1) >> 1) & 1));
        if (tid == 0 && w <= 125) MBAR_EXPECT_TX(barL, TXB);   // re-arm

        // drain step w-1's u partial
        if (tid < 4) {
            float s = 0.f;
#pragma unroll
            for (int q8 = 0; q8 < 8; q8++) s += wsum[rb][q8][tid];
            g_upart[rank][(col0 + tid) * WW + (WW - w)] = s;
        }

        const uint32_t base = lmaddr + (uint32_t)rb * (CC * 8 * 2);
        uint32_t L[8][4];
#pragma unroll
        for (int m8 = 0; m8 < 8; m8++) {
            LDSM_T(L[m8], base + (uint32_t)m8 * 512u);
        }

        float d[4] = {0.f, 0.f, 0.f, 0.f};
        float e[4] = {0.f, 0.f, 0.f, 0.f};
#pragma unroll
        for (int m8 = 0; m8 < 8; m8++) {
            MMA_ASM(d, A[2 * m8],     L[m8][0], L[m8][1]);
            MMA_ASM(e, A[2 * m8 + 1], L[m8][2], L[m8][3]);
        }

        float xa = (j == 0) ? cura.y : (j == 1) ? cura.z : (j == 2) ? cura.w : nxta.x;
        float xb = (j == 0) ? curb.y : (j == 1) ? curb.z : (j == 2) ? curb.w : nxtb.x;

        float s1a = xa + fmaxf(d[0] + e[0], 0.f);
        float s2a = s1a + fmaxf(d[1] + e[1], 0.f);
        float s1b = xb + fmaxf(d[2] + e[2], 0.f);
        float s2b = s1b + fmaxf(d[3] + e[3], 0.f);

        // issue B st.asyncs FIRST (head start on DSMEM flight), then reduce u
        if (w < WW - 1) {
            const uint32_t barWb  = bar32  + (uint32_t)wb * 8u;
            const uint32_t barWbR = bar32r + (uint32_t)wb * 8u;
            const uint32_t bufOff = (uint32_t)wb * (CC * 8 * 2);
            __half2 v0h = __floats2half2_rn(s1a, s2a);
            __half2 v1h = __floats2half2_rn(s1b, s2b);
            uint32_t v0 = *reinterpret_cast<uint32_t*>(&v0h);
            uint32_t v1 = *reinterpret_cast<uint32_t*>(&v1h);
            ST_ASYNC_U32(b32  + bufOff + bo0, v0, barWb);
            ST_ASYNC_U32(b32  + bufOff + bo1, v1, barWb);
            ST_ASYNC_U32(b32r + bufOff + bo0, v0, barWbR);
            ST_ASYNC_U32(b32r + bufOff + bo1, v1, barWbR);

            float usum = w1a * s2a + w1b * s2b;
            usum += __shfl_xor_sync(0xffffffffu, usum, 4);
            usum += __shfl_xor_sync(0xffffffffu, usum, 8);
            usum += __shfl_xor_sync(0xffffffffu, usum, 16);
            if (lane < 4)
                ST_ASYNC_U32(ws32 + (uint32_t)(((wb * 8 + wid) * 4 + lane) * 4),
                             __float_as_uint(usum), barWb);
        } else {
            float usum = w1a * s2a + w1b * s2b;
            usum += __shfl_xor_sync(0xffffffffu, usum, 4);
            usum += __shfl_xor_sync(0xffffffffu, usum, 8);
            usum += __shfl_xor_sync(0xffffffffu, usum, 16);
            if (lane < 4) wsum[1][wid][lane] = usum;   // step 127: plain STS
        }

        if (j == 3) { cura = nxta; curb = nxtb; }
    }

    __syncthreads();
    if (tid < 4) {
        float s = 0.f;
#pragma unroll
        for (int q8 = 0; q8 < 8; q8++) s += wsum[1][q8][tid];
        g_upart[rank][(col0 + tid) * WW + 0] = s;
    }
    CLUSTER_SYNC();
}

// ===========================================================================
__device__ __forceinline__ void stage_rows(float* su0, float* su1,
                                           int b, int i, float& wy) {
    float ys = (float)i * (63.0f / 255.0f);
    int y0 = (int)ys;
    wy = ys - (float)y0;
    int y1 = min(y0 + 1, HH - 1);
    int t = threadIdx.x;
    if (t < 128)
        su0[t] = g_upart[0][(b * HH + y0) * WW + t]
               + g_upart[1][(b * HH + y0) * WW + t];
    else if (t < 256)
        su1[t - 128] = g_upart[0][(b * HH + y1) * WW + (t - 128)]
                     + g_upart[1][(b * HH + y1) * WW + (t - 128)];
}

__device__ __forceinline__ float bilin(const float* su0, const float* su1,
                                       int j, float wy) {
    float xs = (float)j * (127.0f / 511.0f);
    int x0 = (int)xs;
    float wx = xs - (float)x0;
    int x1 = min(x0 + 1, WW - 1);
    float r0 = su0[x0] * (1.f - wy) + su1[x0] * wy;
    float r1 = su0[x1] * (1.f - wy) + su1[x1] * wy;
    return r0 * (1.f - wx) + r1 * wx;
}

__global__ void stats_kernel() {
    __shared__ float su0[128], su1[128];
    __shared__ float rs[8], rq[8];
    int row = blockIdx.x;
    int b = row >> 8, i = row & 255;
    float wy;
    stage_rows(su0, su1, b, i, wy);
    __syncthreads();

    int t = threadIdx.x;
    float sum = 0.f, sq = 0.f;
#pragma unroll
    for (int rr = 0; rr < 2; rr++) {
        float v = bilin(su0, su1, t + rr * 256, wy);
        sum += v;
        sq  += v * v;
    }
#pragma unroll
    for (int o = 16; o; o >>= 1) {
        sum += __shfl_xor_sync(0xffffffffu, sum, o);
        sq  += __shfl_xor_sync(0xffffffffu, sq,  o);
    }
    if ((t & 31) == 0) { rs[t >> 5] = sum; rq[t >> 5] = sq; }
    __syncthreads();
    if (t == 0) {
        float a = 0.f, c = 0.f;
#pragma unroll
        for (int k = 0; k < 8; k++) { a += rs[k]; c += rq[k]; }
        g_psum[row] = a; g_psumsq[row] = c;
    }
}

// output kernel with finalize folded in: every block redundantly reduces the
// 512 partial sums (hot in L2), then applies BN + sigmoid to its row.
__global__ void output_kernel(float* __restrict__ out,
                              const float* __restrict__ gamma,
                              const float* __restrict__ beta) {
    __shared__ float su0[128], su1[128];
    __shared__ float rs[8], rq[8];
    __shared__ float stats2[2];
    int row = blockIdx.x;
    int b = row >> 8, i = row & 255;
    float wy;
    stage_rows(su0, su1, b, i, wy);

    int t = threadIdx.x;
    float sum = g_psum[t] + g_psum[t + 256];
    float sq  = g_psumsq[t] + g_psumsq[t + 256];
#pragma unroll
    for (int o = 16; o; o >>= 1) {
        sum += __shfl_xor_sync(0xffffffffu, sum, o);
        sq  += __shfl_xor_sync(0xffffffffu, sq,  o);
    }
    if ((t & 31) == 0) { rs[t >> 5] = sum; rq[t >> 5] = sq; }
    __syncthreads();
    if (t == 0) {
        float a = 0.f, c = 0.f;
#pragma unroll
        for (int k = 0; k < 8; k++) { a += rs[k]; c += rq[k]; }
        float inv_n = 1.0f / (float)NOUT;
        float mean  = a * inv_n;
        float var   = c * inv_n - mean * mean;
        stats2[0] = mean;
        stats2[1] = rsqrtf(var + 1e-5f);
    }
    __syncthreads();

    float mean = stats2[0], istd = stats2[1];
    float gm = gamma[0], bt = beta[0];
#pragma unroll
    for (int rr = 0; rr < 2; rr++) {
        int j = t + rr * 256;
        float v = bilin(su0, su1, j, wy);
        float y = (v - mean) * istd * gm + bt;
        out[row * WO + j] = 1.0f / (1.0f + expf(-y));
    }
}

// ===========================================================================
extern "C" void kernel_launch(void* const* d_in, const int* in_sizes, int n_in,
                              void* d_out, int out_size) {
    const float* p2    = (const float*)d_in[0];
    const float* convw = (const float*)d_in[1];
    const float* conv1 = (const float*)d_in[2];
    const float* gamma = (const float*)d_in[3];
    const float* beta  = (const float*)d_in[4];
    float* out = (float*)d_out;

    scnn_hmma_kernel<<<64, 256>>>(p2, convw, conv1);
    stats_kernel<<<NROWS, 256>>>();
    output_kernel<<<NROWS, 256>>>(out, gamma, beta);
}

// round 14
// speedup vs baseline: 1.5819x; 1.0907x over previous
#include <cuda_runtime.h>
#include <cuda_fp16.h>
#include <cstdint>

#define CC 256
#define WW 128
#define HH 64
#define BB 2
#define NCOL (BB*HH)
#define HO 256
#define WO 512
#define NOUT (BB*HO*WO)
#define NROWS 512             // output rows (b,i)

// per-fill transaction bytes: 1024 half2 B-state (4096B) + 32 u-partial floats (128B)
#define TXB 4224u

__device__ __half g_M[CC*CC];            // center-tap weights fp16, row-major [o][c]
__device__ float  g_upart[2][NCOL*WW];   // per-rank partial u
__device__ float  g_psum[NROWS];
__device__ float  g_psumsq[NROWS];

__device__ __forceinline__ uint32_t smem_u32(const void* p) {
    uint32_t a;
    asm("{ .reg .u64 t; cvta.to.shared.u64 t, %1; cvt.u32.u64 %0, t; }"
        : "=r"(a) : "l"(p));
    return a;
}
__device__ __forceinline__ uint32_t cluster_rank() {
    uint32_t r;
    asm("mov.u32 %0, %%cluster_ctarank;" : "=r"(r));
    return r;
}
__device__ __forceinline__ uint32_t mapa_u32(uint32_t addr, uint32_t rank) {
    uint32_t r;
    asm("mapa.shared::cluster.u32 %0, %1, %2;" : "=r"(r) : "r"(addr), "r"(rank));
    return r;
}
#define ST_ASYNC_U32(addr, val, mbar)                                         \
    asm volatile("st.async.shared::cluster.mbarrier::complete_tx::bytes.u32 " \
                 "[%0], %1, [%2];" :: "r"(addr), "r"(val), "r"(mbar) : "memory")
#define MBAR_INIT(mbar, cnt)                                                  \
    asm volatile("mbarrier.init.shared.b64 [%0], %1;"                         \
                 :: "r"(mbar), "r"((uint32_t)(cnt)) : "memory")
#define MBAR_EXPECT_TX(mbar, bytes)                                           \
    asm volatile("mbarrier.arrive.expect_tx.shared::cta.b64 _, [%0], %1;"     \
                 :: "r"(mbar), "r"((uint32_t)(bytes)) : "memory")
#define MBAR_WAIT(mbar, parity) do {                                          \
    uint32_t _m = (mbar), _p = (parity), _done;                               \
    asm volatile("{ .reg .pred p;\n\t"                                        \
        "mbarrier.try_wait.parity.acquire.cluster.shared::cta.b64 p, [%1], %2;\n\t" \
        "selp.b32 %0, 1, 0, p; }"                                             \
        : "=r"(_done) : "r"(_m), "r"(_p) : "memory");                         \
    if (!_done) {                                                             \
        asm volatile("{ .reg .pred P1;\n\t"                                   \
            "WL_%=:\n\t"                                                      \
            "mbarrier.try_wait.parity.acquire.cluster.shared::cta.b64 P1, [%0], %1, 0x989680;\n\t" \
            "@P1 bra.uni WD_%=;\n\t"                                          \
            "bra.uni WL_%=;\n\t"                                              \
            "WD_%=: }" :: "r"(_m), "r"(_p) : "memory");                       \
    }                                                                         \
} while (0)
#define CLUSTER_SYNC() do {                                                   \
    asm volatile("barrier.cluster.arrive.aligned;" ::: "memory");             \
    asm volatile("barrier.cluster.wait.aligned;"   ::: "memory");             \
} while (0)

// ===========================================================================
__global__ void extract_M_kernel(const float* __restrict__ convw) {
    int i = blockIdx.x * 256 + threadIdx.x;
    g_M[i] = __float2half(convw[i * 9 + 4]);
}

// ===========================================================================
// 2-CTA-cluster HMMA double scan (R10 structure). 64 CTAs = 32 clusters x
// 4 columns. Each CTA computes 128 output channels (16 MMAs/warp/step).
// Per step each CTA writes its half of the new S into BOTH CTAs' B buffers
// via st.async (tx-counted); one mbarrier per buffer parity, count=1 arrival
// (tid0's expect_tx re-arm) + TXB bytes.
// ONLY change vs R10: accumulators split into FOUR 4-deep chains (d,e,f,g)
// instead of two 8-deep chains, halving the dependent-HMMA latency segment.
#define MMA_ASM(dd, a, b0r, b1r)                                              \
    asm volatile(                                                             \
        "mma.sync.aligned.m16n8k16.row.col.f32.f16.f16.f32 "                  \
        "{%0,%1,%2,%3}, {%4,%5,%6,%7}, {%8,%9}, {%0,%1,%2,%3};"               \
        : "+f"((dd)[0]), "+f"((dd)[1]), "+f"((dd)[2]), "+f"((dd)[3])          \
        : "r"((a)[0]), "r"((a)[1]), "r"((a)[2]), "r"((a)[3]),                 \
          "r"(b0r), "r"(b1r))

__global__ void __launch_bounds__(256, 1) __cluster_dims__(2, 1, 1)
scnn_hmma_kernel(const float* __restrict__ p2, const float* __restrict__ w1g) {
    __shared__ __align__(128) __half Bbuf[2][CC * 8];   // [buf][k*8 + n] 2x4KB
    __shared__ float wsum[2][8][4];
    __shared__ __align__(8) unsigned long long mbar[2];

    const int tid  = threadIdx.x;
    const int wid  = tid >> 5;
    const int lane = tid & 31;
    const int tg   = lane & 3;
    const int g    = lane >> 2;
    const int col0 = (blockIdx.x >> 1) * 4;
    const int col  = col0 + tg;
    const int b    = col >> 6;
    const int h    = col & 63;
    const uint32_t rank = cluster_rank();
    const uint32_t peer = rank ^ 1u;

    // ---- A fragments: this CTA's M rows [rank*128 + 16*wid, +16)
    uint32_t A[16][4];
    const int rlo = (int)rank * 128 + 16 * wid + g;
    {
        const uint32_t* Mlo = reinterpret_cast<const uint32_t*>(g_M + rlo * CC);
        const uint32_t* Mhi = reinterpret_cast<const uint32_t*>(g_M + (rlo + 8) * CC);
#pragma unroll
        for (int kt = 0; kt < 16; kt++) {
            A[kt][0] = Mlo[kt * 8 + tg];
            A[kt][1] = Mhi[kt * 8 + tg];
            A[kt][2] = Mlo[kt * 8 + tg + 4];
            A[kt][3] = Mhi[kt * 8 + tg + 4];
        }
    }

    // this thread's 2 channels (rows g, g+8 of its warp tile)
    const int ch0 = rlo;            // = rank*128 + 16*wid + g
    const int ch1 = rlo + 8;
    const float w1a = w1g[ch0];
    const float w1b = w1g[ch1];

    const float4* xpa = reinterpret_cast<const float4*>(
        p2 + ((size_t)(b * CC + ch0) * HH + h) * WW);
    const float4* xpb = reinterpret_cast<const float4*>(
        p2 + ((size_t)(b * CC + ch1) * HH + h) * WW);

    // smem addresses (local + peer)
    const uint32_t b32    = smem_u32(&Bbuf[0][0]);
    const uint32_t ws32   = smem_u32(&wsum[0][0][0]);
    const uint32_t bar32  = smem_u32(&mbar[0]);
    const uint32_t b32r   = mapa_u32(b32,  peer);
    const uint32_t bar32r = mapa_u32(bar32, peer);
    const uint32_t lmaddr = b32 + (uint32_t)lane * 16u;
    // per-thread B byte offsets for (ch, tg)
    const uint32_t bo0 = (uint32_t)(ch0 * 16 + tg * 4);
    const uint32_t bo1 = (uint32_t)(ch1 * 16 + tg * 4);

    if (tid == 0) { MBAR_INIT(bar32, 1); MBAR_INIT(bar32 + 8, 1); }
    __syncthreads();
    CLUSTER_SYNC();
    if (tid == 0) {
        MBAR_EXPECT_TX(bar32,     TXB);   // fill 0 of buffer 0 (step 0)
        MBAR_EXPECT_TX(bar32 + 8, TXB);   // fill 0 of buffer 1 (step 1)
    }

    // ---- step 0: s1[0] = s2[0] = x[:,0]  -> buffer 0 (both CTAs)
    float4 cura = xpa[0], curb = xpb[0];
    float4 nxta, nxtb;
    {
        float usum = w1a * cura.x + w1b * curb.x;
        usum += __shfl_xor_sync(0xffffffffu, usum, 4);
        usum += __shfl_xor_sync(0xffffffffu, usum, 8);
        usum += __shfl_xor_sync(0xffffffffu, usum, 16);

        __half2 v0h = __halves2half2(__float2half_rn(cura.x), __float2half_rn(cura.x));
        __half2 v1h = __halves2half2(__float2half_rn(curb.x), __float2half_rn(curb.x));
        uint32_t v0 = *reinterpret_cast<uint32_t*>(&v0h);
        uint32_t v1 = *reinterpret_cast<uint32_t*>(&v1h);
        ST_ASYNC_U32(b32  + bo0, v0, bar32);
        ST_ASYNC_U32(b32  + bo1, v1, bar32);
        ST_ASYNC_U32(b32r + bo0, v0, bar32r);
        ST_ASYNC_U32(b32r + bo1, v1, bar32r);
        if (lane < 4)
            ST_ASYNC_U32(ws32 + (uint32_t)((wid * 4 + lane) * 4),
                         __float_as_uint(usum), bar32);
    }

    for (int w = 1; w < WW; w++) {
        const int rb = (w - 1) & 1;
        const int wb = rb ^ 1;
        const uint32_t barL = bar32 + (uint32_t)rb * 8u;
        MBAR_WAIT(barL, (uint32_t)(((w - 1) >> 1) & 1));
        if (tid == 0 && w <= 125) MBAR_EXPECT_TX(barL, TXB);   // re-arm for fill at w+1

        // drain step w-1's u partial
        if (tid < 4) {
            float s = 0.f;
#pragma unroll
            for (int q8 = 0; q8 < 8; q8++) s += wsum[rb][q8][tid];
            g_upart[rank][(col0 + tid) * WW + (WW - w)] = s;
        }

        const uint32_t base = lmaddr + (uint32_t)rb * (CC * 8 * 2);
        uint32_t L[8][4];
#pragma unroll
        for (int m8 = 0; m8 < 8; m8++) {
            asm volatile(
                "ldmatrix.sync.aligned.m8n8.x4.trans.shared.b16 "
                "{%0,%1,%2,%3}, [%4];"
                : "=r"(L[m8][0]), "=r"(L[m8][1]), "=r"(L[m8][2]), "=r"(L[m8][3])
                : "r"(base + (uint32_t)m8 * 512u));
        }

        const int j = (w - 1) & 3;
        if (j == 0 && w + 4 <= WW) {       // prefetch next float4 group
            nxta = xpa[(w + 3) >> 2];
            nxtb = xpb[(w + 3) >> 2];
        }

        // FOUR 4-deep accumulator chains (was two 8-deep)
        float d[4] = {0.f, 0.f, 0.f, 0.f};
        float e[4] = {0.f, 0.f, 0.f, 0.f};
        float f[4] = {0.f, 0.f, 0.f, 0.f};
        float gg[4] = {0.f, 0.f, 0.f, 0.f};
#pragma unroll
        for (int m8 = 0; m8 < 4; m8++) {
            MMA_ASM(d,  A[2 * m8],     L[m8][0], L[m8][1]);
            MMA_ASM(e,  A[2 * m8 + 1], L[m8][2], L[m8][3]);
        }
#pragma unroll
        for (int m8 = 4; m8 < 8; m8++) {
            MMA_ASM(f,  A[2 * m8],     L[m8][0], L[m8][1]);
            MMA_ASM(gg, A[2 * m8 + 1], L[m8][2], L[m8][3]);
        }

        float xa = (j == 0) ? cura.y : (j == 1) ? cura.z : (j == 2) ? cura.w : nxta.x;
        float xb = (j == 0) ? curb.y : (j == 1) ? curb.z : (j == 2) ? curb.w : nxtb.x;

        float s1a = xa + fmaxf((d[0] + e[0]) + (f[0] + gg[0]), 0.f);
        float s2a = s1a + fmaxf((d[1] + e[1]) + (f[1] + gg[1]), 0.f);
        float s1b = xb + fmaxf((d[2] + e[2]) + (f[2] + gg[2]), 0.f);
        float s2b = s1b + fmaxf((d[3] + e[3]) + (f[3] + gg[3]), 0.f);

        float usum = w1a * s2a + w1b * s2b;
        usum += __shfl_xor_sync(0xffffffffu, usum, 4);
        usum += __shfl_xor_sync(0xffffffffu, usum, 8);
        usum += __shfl_xor_sync(0xffffffffu, usum, 16);

        if (w < WW - 1) {
            const uint32_t barWb  = bar32  + (uint32_t)wb * 8u;
            const uint32_t barWbR = bar32r + (uint32_t)wb * 8u;
            const uint32_t bufOff = (uint32_t)wb * (CC * 8 * 2);
            __half2 v0h = __floats2half2_rn(s1a, s2a);
            __half2 v1h = __floats2half2_rn(s1b, s2b);
            uint32_t v0 = *reinterpret_cast<uint32_t*>(&v0h);
            uint32_t v1 = *reinterpret_cast<uint32_t*>(&v1h);
            ST_ASYNC_U32(b32  + bufOff + bo0, v0, barWb);
            ST_ASYNC_U32(b32  + bufOff + bo1, v1, barWb);
            ST_ASYNC_U32(b32r + bufOff + bo0, v0, barWbR);
            ST_ASYNC_U32(b32r + bufOff + bo1, v1, barWbR);
            if (lane < 4)
                ST_ASYNC_U32(ws32 + (uint32_t)(((wb * 8 + wid) * 4 + lane) * 4),
                             __float_as_uint(usum), barWb);
        } else {
            if (lane < 4) wsum[1][wid][lane] = usum;   // step 127: plain STS
        }

        if (j == 3) { cura = nxta; curb = nxtb; }
    }

    __syncthreads();
    if (tid < 4) {
        float s = 0.f;
#pragma unroll
        for (int q8 = 0; q8 < 8; q8++) s += wsum[1][q8][tid];
        g_upart[rank][(col0 + tid) * WW + 0] = s;
    }
    CLUSTER_SYNC();
}

// ===========================================================================
__device__ __forceinline__ void stage_rows(float* su0, float* su1,
                                           int b, int i, float& wy) {
    float ys = (float)i * (63.0f / 255.0f);
    int y0 = (int)ys;
    wy = ys - (float)y0;
    int y1 = min(y0 + 1, HH - 1);
    int t = threadIdx.x;
    if (t < 128)
        su0[t] = g_upart[0][(b * HH + y0) * WW + t]
               + g_upart[1][(b * HH + y0) * WW + t];
    else if (t < 256)
        su1[t - 128] = g_upart[0][(b * HH + y1) * WW + (t - 128)]
                     + g_upart[1][(b * HH + y1) * WW + (t - 128)];
}

__device__ __forceinline__ float bilin(const float* su0, const float* su1,
                                       int j, float wy) {
    float xs = (float)j * (127.0f / 511.0f);
    int x0 = (int)xs;
    float wx = xs - (float)x0;
    int x1 = min(x0 + 1, WW - 1);
    float r0 = su0[x0] * (1.f - wy) + su1[x0] * wy;
    float r1 = su0[x1] * (1.f - wy) + su1[x1] * wy;
    return r0 * (1.f - wx) + r1 * wx;
}

__global__ void stats_kernel() {
    __shared__ float su0[128], su1[128];
    __shared__ float rs[8], rq[8];
    int row = blockIdx.x;
    int b = row >> 8, i = row & 255;
    float wy;
    stage_rows(su0, su1, b, i, wy);
    __syncthreads();

    int t = threadIdx.x;
    float sum = 0.f, sq = 0.f;
#pragma unroll
    for (int rr = 0; rr < 2; rr++) {
        float v = bilin(su0, su1, t + rr * 256, wy);
        sum += v;
        sq  += v * v;
    }
#pragma unroll
    for (int o = 16; o; o >>= 1) {
        sum += __shfl_xor_sync(0xffffffffu, sum, o);
        sq  += __shfl_xor_sync(0xffffffffu, sq,  o);
    }
    if ((t & 31) == 0) { rs[t >> 5] = sum; rq[t >> 5] = sq; }
    __syncthreads();
    if (t == 0) {
        float a = 0.f, c = 0.f;
#pragma unroll
        for (int k = 0; k < 8; k++) { a += rs[k]; c += rq[k]; }
        g_psum[row] = a; g_psumsq[row] = c;
    }
}

// output kernel with finalize folded in: every block redundantly reduces the
// 512 partial sums (hot in L2), then applies BN + sigmoid to its row.
__global__ void output_kernel(float* __restrict__ out,
                              const float* __restrict__ gamma,
                              const float* __restrict__ beta) {
    __shared__ float su0[128], su1[128];
    __shared__ float rs[8], rq[8];
    __shared__ float stats2[2];
    int row = blockIdx.x;
    int b = row >> 8, i = row & 255;
    float wy;
    stage_rows(su0, su1, b, i, wy);

    int t = threadIdx.x;
    float sum = g_psum[t] + g_psum[t + 256];
    float sq  = g_psumsq[t] + g_psumsq[t + 256];
#pragma unroll
    for (int o = 16; o; o >>= 1) {
        sum += __shfl_xor_sync(0xffffffffu, sum, o);
        sq  += __shfl_xor_sync(0xffffffffu, sq,  o);
    }
    if ((t & 31) == 0) { rs[t >> 5] = sum; rq[t >> 5] = sq; }
    __syncthreads();
    if (t == 0) {
        float a = 0.f, c = 0.f;
#pragma unroll
        for (int k = 0; k < 8; k++) { a += rs[k]; c += rq[k]; }
        float inv_n = 1.0f / (float)NOUT;
        float mean  = a * inv_n;
        float var   = c * inv_n - mean * mean;
        stats2[0] = mean;
        stats2[1] = rsqrtf(var + 1e-5f);
    }
    __syncthreads();

    float mean = stats2[0], istd = stats2[1];
    float gm = gamma[0], bt = beta[0];
#pragma unroll
    for (int rr = 0; rr < 2; rr++) {
        int j = t + rr * 256;
        float v = bilin(su0, su1, j, wy);
        float y = (v - mean) * istd * gm + bt;
        out[row * WO + j] = 1.0f / (1.0f + expf(-y));
    }
}

// ===========================================================================
extern "C" void kernel_launch(void* const* d_in, const int* in_sizes, int n_in,
                              void* d_out, int out_size) {
    const float* p2    = (const float*)d_in[0];
    const float* convw = (const float*)d_in[1];
    const float* conv1 = (const float*)d_in[2];
    const float* gamma = (const float*)d_in[3];
    const float* beta  = (const float*)d_in[4];
    float* out = (float*)d_out;

    extract_M_kernel<<<256, 256>>>(convw);
    scnn_hmma_kernel<<<64, 256>>>(p2, conv1);
    stats_kernel<<<NROWS, 256>>>();
    output_kernel<<<NROWS, 256>>>(out, gamma, beta);
}

// round 15
// speedup vs baseline: 1.5826x; 1.0004x over previous
#include <cuda_runtime.h>
#include <cuda_fp16.h>
#include <cstdint>

#define CC 256
#define WW 128
#define HH 64
#define BB 2
#define NCOL (BB*HH)
#define HO 256
#define WO 512
#define NOUT (BB*HO*WO)
#define NROWS 512             // output rows (b,i)
#define NBLK 64               // scan CTAs

// per-fill transaction bytes: 1024 half2 B-state only (4096B)
#define TXB 4096u

__device__ __half g_M[CC*CC];            // center-tap weights fp16, row-major [o][c]
__device__ float  g_part[WW*NBLK*256];   // per-thread u partials [w][blk][tid] 8MB
__device__ float  g_u[NCOL*WW];          // reduced (1-channel) pre-upsample result
__device__ float  g_psum[NROWS];
__device__ float  g_psumsq[NROWS];

__device__ __forceinline__ uint32_t smem_u32(const void* p) {
    uint32_t a;
    asm("{ .reg .u64 t; cvta.to.shared.u64 t, %1; cvt.u32.u64 %0, t; }"
        : "=r"(a) : "l"(p));
    return a;
}
__device__ __forceinline__ uint32_t cluster_rank() {
    uint32_t r;
    asm("mov.u32 %0, %%cluster_ctarank;" : "=r"(r));
    return r;
}
__device__ __forceinline__ uint32_t mapa_u32(uint32_t addr, uint32_t rank) {
    uint32_t r;
    asm("mapa.shared::cluster.u32 %0, %1, %2;" : "=r"(r) : "r"(addr), "r"(rank));
    return r;
}
#define ST_ASYNC_U32(addr, val, mbar)                                         \
    asm volatile("st.async.shared::cluster.mbarrier::complete_tx::bytes.u32 " \
                 "[%0], %1, [%2];" :: "r"(addr), "r"(val), "r"(mbar) : "memory")
#define MBAR_INIT(mbar, cnt)                                                  \
    asm volatile("mbarrier.init.shared.b64 [%0], %1;"                         \
                 :: "r"(mbar), "r"((uint32_t)(cnt)) : "memory")
#define MBAR_EXPECT_TX(mbar, bytes)                                           \
    asm volatile("mbarrier.arrive.expect_tx.shared::cta.b64 _, [%0], %1;"     \
                 :: "r"(mbar), "r"((uint32_t)(bytes)) : "memory")
#define MBAR_WAIT(mbar, parity) do {                                          \
    uint32_t _m = (mbar), _p = (parity), _done;                               \
    asm volatile("{ .reg .pred p;\n\t"                                        \
        "mbarrier.try_wait.parity.acquire.cluster.shared::cta.b64 p, [%1], %2;\n\t" \
        "selp.b32 %0, 1, 0, p; }"                                             \
        : "=r"(_done) : "r"(_m), "r"(_p) : "memory");                         \
    if (!_done) {                                                             \
        asm volatile("{ .reg .pred P1;\n\t"                                   \
            "WL_%=:\n\t"                                                      \
            "mbarrier.try_wait.parity.acquire.cluster.shared::cta.b64 P1, [%0], %1, 0x989680;\n\t" \
            "@P1 bra.uni WD_%=;\n\t"                                          \
            "bra.uni WL_%=;\n\t"                                              \
            "WD_%=: }" :: "r"(_m), "r"(_p) : "memory");                       \
    }                                                                         \
} while (0)
#define CLUSTER_SYNC() do {                                                   \
    asm volatile("barrier.cluster.arrive.aligned;" ::: "memory");             \
    asm volatile("barrier.cluster.wait.aligned;"   ::: "memory");             \
} while (0)

// ===========================================================================
__global__ void extract_M_kernel(const float* __restrict__ convw) {
    int i = blockIdx.x * 256 + threadIdx.x;
    g_M[i] = __float2half(convw[i * 9 + 4]);
}

// ===========================================================================
// 2-CTA-cluster HMMA double scan (R14 structure). 64 CTAs = 32 clusters x
// 4 columns. Each CTA computes 128 output channels (16 MMAs/warp/step) as
// FOUR 4-deep accumulator chains. Per step each CTA writes its half of the
// new S into BOTH CTAs' B buffers via st.async (tx-counted, TXB=4096).
// ONLY change vs R14: the u-reduction is REMOVED from the loop — each thread
// fires one STG.32 of its fp32 partial to g_part (off the critical path);
// a separate reduce kernel produces g_u.
#define MMA_ASM(dd, a, b0r, b1r)                                              \
    asm volatile(                                                             \
        "mma.sync.aligned.m16n8k16.row.col.f32.f16.f16.f32 "                  \
        "{%0,%1,%2,%3}, {%4,%5,%6,%7}, {%8,%9}, {%0,%1,%2,%3};"               \
        : "+f"((dd)[0]), "+f"((dd)[1]), "+f"((dd)[2]), "+f"((dd)[3])          \
        : "r"((a)[0]), "r"((a)[1]), "r"((a)[2]), "r"((a)[3]),                 \
          "r"(b0r), "r"(b1r))

__global__ void __launch_bounds__(256, 1) __cluster_dims__(2, 1, 1)
scnn_hmma_kernel(const float* __restrict__ p2, const float* __restrict__ w1g) {
    __shared__ __align__(128) __half Bbuf[2][CC * 8];   // [buf][k*8 + n] 2x4KB
    __shared__ __align__(8) unsigned long long mbar[2];

    const int tid  = threadIdx.x;
    const int wid  = tid >> 5;
    const int lane = tid & 31;
    const int tg   = lane & 3;
    const int g    = lane >> 2;
    const int col0 = (blockIdx.x >> 1) * 4;
    const int col  = col0 + tg;
    const int b    = col >> 6;
    const int h    = col & 63;
    const uint32_t rank = cluster_rank();
    const uint32_t peer = rank ^ 1u;

    // ---- A fragments: this CTA's M rows [rank*128 + 16*wid, +16)
    uint32_t A[16][4];
    const int rlo = (int)rank * 128 + 16 * wid + g;
    {
        const uint32_t* Mlo = reinterpret_cast<const uint32_t*>(g_M + rlo * CC);
        const uint32_t* Mhi = reinterpret_cast<const uint32_t*>(g_M + (rlo + 8) * CC);
#pragma unroll
        for (int kt = 0; kt < 16; kt++) {
            A[kt][0] = Mlo[kt * 8 + tg];
            A[kt][1] = Mhi[kt * 8 + tg];
            A[kt][2] = Mlo[kt * 8 + tg + 4];
            A[kt][3] = Mhi[kt * 8 + tg + 4];
        }
    }

    // this thread's 2 channels (rows g, g+8 of its warp tile)
    const int ch0 = rlo;            // = rank*128 + 16*wid + g
    const int ch1 = rlo + 8;
    const float w1a = w1g[ch0];
    const float w1b = w1g[ch1];

    const float4* xpa = reinterpret_cast<const float4*>(
        p2 + ((size_t)(b * CC + ch0) * HH + h) * WW);
    const float4* xpb = reinterpret_cast<const float4*>(
        p2 + ((size_t)(b * CC + ch1) * HH + h) * WW);

    // u-partial output stream: g_part[w][blk][tid], fire-and-forget STG
    float* gpart = g_part + (size_t)blockIdx.x * 256 + tid;

    // smem addresses (local + peer)
    const uint32_t b32    = smem_u32(&Bbuf[0][0]);
    const uint32_t bar32  = smem_u32(&mbar[0]);
    const uint32_t b32r   = mapa_u32(b32,  peer);
    const uint32_t bar32r = mapa_u32(bar32, peer);
    const uint32_t lmaddr = b32 + (uint32_t)lane * 16u;
    // per-thread B byte offsets for (ch, tg)
    const uint32_t bo0 = (uint32_t)(ch0 * 16 + tg * 4);
    const uint32_t bo1 = (uint32_t)(ch1 * 16 + tg * 4);

    if (tid == 0) { MBAR_INIT(bar32, 1); MBAR_INIT(bar32 + 8, 1); }
    __syncthreads();
    CLUSTER_SYNC();
    if (tid == 0) {
        MBAR_EXPECT_TX(bar32,     TXB);   // fill 0 of buffer 0 (step 0)
        MBAR_EXPECT_TX(bar32 + 8, TXB);   // fill 0 of buffer 1 (step 1)
    }

    // ---- step 0: s1[0] = s2[0] = x[:,0]  -> buffer 0 (both CTAs)
    float4 cura = xpa[0], curb = xpb[0];
    float4 nxta, nxtb;
    {
        __half2 v0h = __halves2half2(__float2half_rn(cura.x), __float2half_rn(cura.x));
        __half2 v1h = __halves2half2(__float2half_rn(curb.x), __float2half_rn(curb.x));
        uint32_t v0 = *reinterpret_cast<uint32_t*>(&v0h);
        uint32_t v1 = *reinterpret_cast<uint32_t*>(&v1h);
        ST_ASYNC_U32(b32  + bo0, v0, bar32);
        ST_ASYNC_U32(b32  + bo1, v1, bar32);
        ST_ASYNC_U32(b32r + bo0, v0, bar32r);
        ST_ASYNC_U32(b32r + bo1, v1, bar32r);
        gpart[0] = w1a * cura.x + w1b * curb.x;
    }

    for (int w = 1; w < WW; w++) {
        const int rb = (w - 1) & 1;
        const int wb = rb ^ 1;
        const uint32_t barL = bar32 + (uint32_t)rb * 8u;
        MBAR_WAIT(barL, (uint32_t)(((w - 1) >> 1) & 1));
        if (tid == 0 && w <= 125) MBAR_EXPECT_TX(barL, TXB);   // re-arm for fill at w+1

        const uint32_t base = lmaddr + (uint32_t)rb * (CC * 8 * 2);
        uint32_t L[8][4];
#pragma unroll
        for (int m8 = 0; m8 < 8; m8++) {
            asm volatile(
                "ldmatrix.sync.aligned.m8n8.x4.trans.shared.b16 "
                "{%0,%1,%2,%3}, [%4];"
                : "=r"(L[m8][0]), "=r"(L[m8][1]), "=r"(L[m8][2]), "=r"(L[m8][3])
                : "r"(base + (uint32_t)m8 * 512u));
        }

        const int j = (w - 1) & 3;
        if (j == 0 && w + 4 <= WW) {       // prefetch next float4 group
            nxta = xpa[(w + 3) >> 2];
            nxtb = xpb[(w + 3) >> 2];
        }

        // FOUR 4-deep accumulator chains
        float d[4] = {0.f, 0.f, 0.f, 0.f};
        float e[4] = {0.f, 0.f, 0.f, 0.f};
        float f[4] = {0.f, 0.f, 0.f, 0.f};
        float gg[4] = {0.f, 0.f, 0.f, 0.f};
#pragma unroll
        for (int m8 = 0; m8 < 4; m8++) {
            MMA_ASM(d,  A[2 * m8],     L[m8][0], L[m8][1]);
            MMA_ASM(e,  A[2 * m8 + 1], L[m8][2], L[m8][3]);
        }
#pragma unroll
        for (int m8 = 4; m8 < 8; m8++) {
            MMA_ASM(f,  A[2 * m8],     L[m8][0], L[m8][1]);
            MMA_ASM(gg, A[2 * m8 + 1], L[m8][2], L[m8][3]);
        }

        float xa = (j == 0) ? cura.y : (j == 1) ? cura.z : (j == 2) ? cura.w : nxta.x;
        float xb = (j == 0) ? curb.y : (j == 1) ? curb.z : (j == 2) ? curb.w : nxtb.x;

        float s1a = xa + fmaxf((d[0] + e[0]) + (f[0] + gg[0]), 0.f);
        float s2a = s1a + fmaxf((d[1] + e[1]) + (f[1] + gg[1]), 0.f);
        float s1b = xb + fmaxf((d[2] + e[2]) + (f[2] + gg[2]), 0.f);
        float s2b = s1b + fmaxf((d[3] + e[3]) + (f[3] + gg[3]), 0.f);

        // B st.asyncs first (they gate the peer's next step), then the
        // fire-and-forget u-partial STG.
        if (w < WW - 1) {
            const uint32_t barWb  = bar32  + (uint32_t)wb * 8u;
            const uint32_t barWbR = bar32r + (uint32_t)wb * 8u;
            const uint32_t bufOff = (uint32_t)wb * (CC * 8 * 2);
            __half2 v0h = __floats2half2_rn(s1a, s2a);
            __half2 v1h = __floats2half2_rn(s1b, s2b);
            uint32_t v0 = *reinterpret_cast<uint32_t*>(&v0h);
            uint32_t v1 = *reinterpret_cast<uint32_t*>(&v1h);
            ST_ASYNC_U32(b32  + bufOff + bo0, v0, barWb);
            ST_ASYNC_U32(b32  + bufOff + bo1, v1, barWb);
            ST_ASYNC_U32(b32r + bufOff + bo0, v0, barWbR);
            ST_ASYNC_U32(b32r + bufOff + bo1, v1, barWbR);
        }
        gpart[(size_t)w * (NBLK * 256)] = w1a * s2a + w1b * s2b;

        if (j == 3) { cura = nxta; curb = nxtb; }
    }

    CLUSTER_SYNC();
}

// ===========================================================================
// Reduce u: g_u[col][127-w] = sum over (rank, wid, g) of g_part[w][blk][tid].
// grid = 128 (w), block = 128 (col). Deterministic fixed-order summation.
__global__ void reduce_u_kernel() {
    int w = blockIdx.x;
    int c = threadIdx.x;              // column 0..127
    int tg = c & 3;
    int cg = c >> 2;                  // cluster 0..31
    const float* base = g_part + (size_t)w * (NBLK * 256);
    float s = 0.f;
#pragma unroll
    for (int rank = 0; rank < 2; rank++) {
        const float* pb = base + (cg * 2 + rank) * 256 + tg;
#pragma unroll
        for (int q = 0; q < 64; q++)      // wid*8 + g, stride 4 in tid
            s += pb[q * 4];
    }
    g_u[c * WW + (WW - 1 - w)] = s;
}

// ===========================================================================
__device__ __forceinline__ void stage_rows(float* su0, float* su1,
                                           int b, int i, float& wy) {
    float ys = (float)i * (63.0f / 255.0f);
    int y0 = (int)ys;
    wy = ys - (float)y0;
    int y1 = min(y0 + 1, HH - 1);
    int t = threadIdx.x;
    if (t < 128)      su0[t]       = g_u[(b * HH + y0) * WW + t];
    else if (t < 256) su1[t - 128] = g_u[(b * HH + y1) * WW + (t - 128)];
}

__device__ __forceinline__ float bilin(const float* su0, const float* su1,
                                       int j, float wy) {
    float xs = (float)j * (127.0f / 511.0f);
    int x0 = (int)xs;
    float wx = xs - (float)x0;
    int x1 = min(x0 + 1, WW - 1);
    float r0 = su0[x0] * (1.f - wy) + su1[x0] * wy;
    float r1 = su0[x1] * (1.f - wy) + su1[x1] * wy;
    return r0 * (1.f - wx) + r1 * wx;
}

__global__ void stats_kernel() {
    __shared__ float su0[128], su1[128];
    __shared__ float rs[8], rq[8];
    int row = blockIdx.x;
    int b = row >> 8, i = row & 255;
    float wy;
    stage_rows(su0, su1, b, i, wy);
    __syncthreads();

    int t = threadIdx.x;
    float sum = 0.f, sq = 0.f;
#pragma unroll
    for (int rr = 0; rr < 2; rr++) {
        float v = bilin(su0, su1, t + rr * 256, wy);
        sum += v;
        sq  += v * v;
    }
#pragma unroll
    for (int o = 16; o; o >>= 1) {
        sum += __shfl_xor_sync(0xffffffffu, sum, o);
        sq  += __shfl_xor_sync(0xffffffffu, sq,  o);
    }
    if ((t & 31) == 0) { rs[t >> 5] = sum; rq[t >> 5] = sq; }
    __syncthreads();
    if (t == 0) {
        float a = 0.f, c = 0.f;
#pragma unroll
        for (int k = 0; k < 8; k++) { a += rs[k]; c += rq[k]; }
        g_psum[row] = a; g_psumsq[row] = c;
    }
}

// output kernel with finalize folded in: every block redundantly reduces the
// 512 partial sums (hot in L2), then applies BN + sigmoid to its row.
__global__ void output_kernel(float* __restrict__ out,
                              const float* __restrict__ gamma,
                              const float* __restrict__ beta) {
    __shared__ float su0[128], su1[128];
    __shared__ float rs[8], rq[8];
    __shared__ float stats2[2];
    int row = blockIdx.x;
    int b = row >> 8, i = row & 255;
    float wy;
    stage_rows(su0, su1, b, i, wy);

    int t = threadIdx.x;
    float sum = g_psum[t] + g_psum[t + 256];
    float sq  = g_psumsq[t] + g_psumsq[t + 256];
#pragma unroll
    for (int o = 16; o; o >>= 1) {
        sum += __shfl_xor_sync(0xffffffffu, sum, o);
        sq  += __shfl_xor_sync(0xffffffffu, sq,  o);
    }
    if ((t & 31) == 0) { rs[t >> 5] = sum; rq[t >> 5] = sq; }
    __syncthreads();
    if (t == 0) {
        float a = 0.f, c = 0.f;
#pragma unroll
        for (int k = 0; k < 8; k++) { a += rs[k]; c += rq[k]; }
        float inv_n = 1.0f / (float)NOUT;
        float mean  = a * inv_n;
        float var   = c * inv_n - mean * mean;
        stats2[0] = mean;
        stats2[1] = rsqrtf(var + 1e-5f);
    }
    __syncthreads();

    float mean = stats2[0], istd = stats2[1];
    float gm = gamma[0], bt = beta[0];
#pragma unroll
    for (int rr = 0; rr < 2; rr++) {
        int j = t + rr * 256;
        float v = bilin(su0, su1, j, wy);
        float y = (v - mean) * istd * gm + bt;
        out[row * WO + j] = 1.0f / (1.0f + expf(-y));
    }
}

// ===========================================================================
extern "C" void kernel_launch(void* const* d_in, const int* in_sizes, int n_in,
                              void* d_out, int out_size) {
    const float* p2    = (const float*)d_in[0];
    const float* convw = (const float*)d_in[1];
    const float* conv1 = (const float*)d_in[2];
    const float* gamma = (const float*)d_in[3];
    const float* beta  = (const float*)d_in[4];
    float* out = (float*)d_out;

    extract_M_kernel<<<256, 256>>>(convw);
    scnn_hmma_kernel<<<NBLK, 256>>>(p2, conv1);
    reduce_u_kernel<<<WW, 128>>>();
    stats_kernel<<<NROWS, 256>>>();
    output_kernel<<<NROWS, 256>>>(out, gamma, beta);
}

// round 16
// speedup vs baseline: 1.8191x; 1.1494x over previous
#include <cuda_runtime.h>
#include <cuda_fp16.h>
#include <cstdint>

#define CC 256
#define WW 128
#define HH 64
#define BB 2
#define NCOL (BB*HH)
#define HO 256
#define WO 512
#define NOUT (BB*HO*WO)
#define NROWS 512             // output rows (b,i)
#define NBLK 128              // scan CTAs (32 clusters x 4)
#define CLW 4                 // cluster width

// per-fill transaction bytes: full B buffer = 256 rows x 16B = 4096
#define TXB 4096u

__device__ __half g_M[CC*CC];            // center-tap weights fp16, row-major [o][c]
__device__ float  g_part[WW*NBLK*128];   // per-thread u partials [w][blk][tid] 8MB
__device__ float  g_u[NCOL*WW];          // reduced (1-channel) pre-upsample result
__device__ float  g_psum[NROWS];
__device__ float  g_psumsq[NROWS];

__device__ __forceinline__ uint32_t smem_u32(const void* p) {
    uint32_t a;
    asm("{ .reg .u64 t; cvta.to.shared.u64 t, %1; cvt.u32.u64 %0, t; }"
        : "=r"(a) : "l"(p));
    return a;
}
__device__ __forceinline__ uint32_t cluster_rank() {
    uint32_t r;
    asm("mov.u32 %0, %%cluster_ctarank;" : "=r"(r));
    return r;
}
__device__ __forceinline__ uint32_t mapa_u32(uint32_t addr, uint32_t rank) {
    uint32_t r;
    asm("mapa.shared::cluster.u32 %0, %1, %2;" : "=r"(r) : "r"(addr), "r"(rank));
    return r;
}
#define ST_ASYNC_U32(addr, val, mbar)                                         \
    asm volatile("st.async.shared::cluster.mbarrier::complete_tx::bytes.u32 " \
                 "[%0], %1, [%2];" :: "r"(addr), "r"(val), "r"(mbar) : "memory")
#define MBAR_INIT(mbar, cnt)                                                  \
    asm volatile("mbarrier.init.shared.b64 [%0], %1;"                         \
                 :: "r"(mbar), "r"((uint32_t)(cnt)) : "memory")
#define MBAR_EXPECT_TX(mbar, bytes)                                           \
    asm volatile("mbarrier.arrive.expect_tx.shared::cta.b64 _, [%0], %1;"     \
                 :: "r"(mbar), "r"((uint32_t)(bytes)) : "memory")
#define MBAR_WAIT(mbar, parity) do {                                          \
    uint32_t _m = (mbar), _p = (parity), _done;                               \
    asm volatile("{ .reg .pred p;\n\t"                                        \
        "mbarrier.try_wait.parity.acquire.cluster.shared::cta.b64 p, [%1], %2;\n\t" \
        "selp.b32 %0, 1, 0, p; }"                                             \
        : "=r"(_done) : "r"(_m), "r"(_p) : "memory");                         \
    if (!_done) {                                                             \
        asm volatile("{ .reg .pred P1;\n\t"                                   \
            "WL_%=:\n\t"                                                      \
            "mbarrier.try_wait.parity.acquire.cluster.shared::cta.b64 P1, [%0], %1, 0x989680;\n\t" \
            "@P1 bra.uni WD_%=;\n\t"                                          \
            "bra.uni WL_%=;\n\t"                                              \
            "WD_%=: }" :: "r"(_m), "r"(_p) : "memory");                       \
    }                                                                         \
} while (0)
#define CLUSTER_SYNC() do {                                                   \
    asm volatile("barrier.cluster.arrive.aligned;" ::: "memory");             \
    asm volatile("barrier.cluster.wait.aligned;"   ::: "memory");             \
} while (0)

// ===========================================================================
__global__ void extract_M_kernel(const float* __restrict__ convw) {
    int i = blockIdx.x * 256 + threadIdx.x;
    g_M[i] = __float2half(convw[i * 9 + 4]);
}

// ===========================================================================
// 4-CTA-cluster HMMA double scan. 128 CTAs = 32 clusters x 4 columns.
// Each CTA computes 64 output channels with 128 threads (4 warps, 1/SMSP);
// each warp keeps its full 16-row x K=256 tile, so the loop body (LDSM block,
// FOUR 4-deep MMA chains, epilogue) is identical to R15. Per step each CTA
// st.asyncs its 64 channels of new S into ALL FOUR CTAs' B buffers
// (8 st.asyncs/thread, TXB=4096 per buffer fill).
#define MMA_ASM(dd, a, b0r, b1r)                                              \
    asm volatile(                                                             \
        "mma.sync.aligned.m16n8k16.row.col.f32.f16.f16.f32 "                  \
        "{%0,%1,%2,%3}, {%4,%5,%6,%7}, {%8,%9}, {%0,%1,%2,%3};"               \
        : "+f"((dd)[0]), "+f"((dd)[1]), "+f"((dd)[2]), "+f"((dd)[3])          \
        : "r"((a)[0]), "r"((a)[1]), "r"((a)[2]), "r"((a)[3]),                 \
          "r"(b0r), "r"(b1r))

__global__ void __launch_bounds__(128, 1) __cluster_dims__(CLW, 1, 1)
scnn_hmma_kernel(const float* __restrict__ p2, const float* __restrict__ w1g) {
    __shared__ __align__(128) __half Bbuf[2][CC * 8];   // [buf][k*8 + n] 2x4KB
    __shared__ __align__(8) unsigned long long mbar[2];

    const int tid  = threadIdx.x;
    const int wid  = tid >> 5;          // 0..3
    const int lane = tid & 31;
    const int tg   = lane & 3;
    const int g    = lane >> 2;
    const int col0 = (blockIdx.x >> 2) * 4;
    const int col  = col0 + tg;
    const int b    = col >> 6;
    const int h    = col & 63;
    const uint32_t rank = cluster_rank();   // 0..3

    // ---- A fragments: this CTA's M rows [rank*64 + 16*wid, +16)
    uint32_t A[16][4];
    const int rlo = (int)rank * 64 + 16 * wid + g;
    {
        const uint32_t* Mlo = reinterpret_cast<const uint32_t*>(g_M + rlo * CC);
        const uint32_t* Mhi = reinterpret_cast<const uint32_t*>(g_M + (rlo + 8) * CC);
#pragma unroll
        for (int kt = 0; kt < 16; kt++) {
            A[kt][0] = Mlo[kt * 8 + tg];
            A[kt][1] = Mhi[kt * 8 + tg];
            A[kt][2] = Mlo[kt * 8 + tg + 4];
            A[kt][3] = Mhi[kt * 8 + tg + 4];
        }
    }

    // this thread's 2 channels (rows g, g+8 of its warp tile)
    const int ch0 = rlo;
    const int ch1 = rlo + 8;
    const float w1a = w1g[ch0];
    const float w1b = w1g[ch1];

    const float4* xpa = reinterpret_cast<const float4*>(
        p2 + ((size_t)(b * CC + ch0) * HH + h) * WW);
    const float4* xpb = reinterpret_cast<const float4*>(
        p2 + ((size_t)(b * CC + ch1) * HH + h) * WW);

    // u-partial output stream: g_part[w][blk][tid], fire-and-forget STG
    float* gpart = g_part + (size_t)blockIdx.x * 128 + tid;

    // smem addresses: local + all 4 cluster ranks (mapa to self is legal)
    const uint32_t b32   = smem_u32(&Bbuf[0][0]);
    const uint32_t bar32 = smem_u32(&mbar[0]);
    uint32_t bAll[CLW], barAll[CLW];
#pragma unroll
    for (int r = 0; r < CLW; r++) {
        bAll[r]   = mapa_u32(b32,   (uint32_t)r);
        barAll[r] = mapa_u32(bar32, (uint32_t)r);
    }
    const uint32_t lmaddr = b32 + (uint32_t)lane * 16u;
    const uint32_t bo0 = (uint32_t)(ch0 * 16 + tg * 4);
    const uint32_t bo1 = (uint32_t)(ch1 * 16 + tg * 4);

    if (tid == 0) { MBAR_INIT(bar32, 1); MBAR_INIT(bar32 + 8, 1); }
    __syncthreads();
    CLUSTER_SYNC();
    if (tid == 0) {
        MBAR_EXPECT_TX(bar32,     TXB);   // fill 0 of buffer 0 (step 0)
        MBAR_EXPECT_TX(bar32 + 8, TXB);   // fill 0 of buffer 1 (step 1)
    }

    // ---- step 0: s1[0] = s2[0] = x[:,0]  -> buffer 0 (all 4 CTAs)
    float4 cura = xpa[0], curb = xpb[0];
    float4 nxta, nxtb;
    {
        __half2 v0h = __halves2half2(__float2half_rn(cura.x), __float2half_rn(cura.x));
        __half2 v1h = __halves2half2(__float2half_rn(curb.x), __float2half_rn(curb.x));
        uint32_t v0 = *reinterpret_cast<uint32_t*>(&v0h);
        uint32_t v1 = *reinterpret_cast<uint32_t*>(&v1h);
#pragma unroll
        for (int r = 0; r < CLW; r++) {
            ST_ASYNC_U32(bAll[r] + bo0, v0, barAll[r]);
            ST_ASYNC_U32(bAll[r] + bo1, v1, barAll[r]);
        }
        gpart[0] = w1a * cura.x + w1b * curb.x;
    }

    for (int w = 1; w < WW; w++) {
        const int rb = (w - 1) & 1;
        const int wb = rb ^ 1;
        const uint32_t barL = bar32 + (uint32_t)rb * 8u;
        MBAR_WAIT(barL, (uint32_t)(((w - 1) >> 1) & 1));
        if (tid == 0 && w <= 125) MBAR_EXPECT_TX(barL, TXB);   // re-arm for fill at w+1

        const uint32_t base = lmaddr + (uint32_t)rb * (CC * 8 * 2);
        uint32_t L[8][4];
#pragma unroll
        for (int m8 = 0; m8 < 8; m8++) {
            asm volatile(
                "ldmatrix.sync.aligned.m8n8.x4.trans.shared.b16 "
                "{%0,%1,%2,%3}, [%4];"
                : "=r"(L[m8][0]), "=r"(L[m8][1]), "=r"(L[m8][2]), "=r"(L[m8][3])
                : "r"(base + (uint32_t)m8 * 512u));
        }

        const int j = (w - 1) & 3;
        if (j == 0 && w + 4 <= WW) {       // prefetch next float4 group
            nxta = xpa[(w + 3) >> 2];
            nxtb = xpb[(w + 3) >> 2];
        }

        // FOUR 4-deep accumulator chains (identical to R15)
        float d[4] = {0.f, 0.f, 0.f, 0.f};
        float e[4] = {0.f, 0.f, 0.f, 0.f};
        float f[4] = {0.f, 0.f, 0.f, 0.f};
        float gg[4] = {0.f, 0.f, 0.f, 0.f};
#pragma unroll
        for (int m8 = 0; m8 < 4; m8++) {
            MMA_ASM(d,  A[2 * m8],     L[m8][0], L[m8][1]);
            MMA_ASM(e,  A[2 * m8 + 1], L[m8][2], L[m8][3]);
        }
#pragma unroll
        for (int m8 = 4; m8 < 8; m8++) {
            MMA_ASM(f,  A[2 * m8],     L[m8][0], L[m8][1]);
            MMA_ASM(gg, A[2 * m8 + 1], L[m8][2], L[m8][3]);
        }

        float xa = (j == 0) ? cura.y : (j == 1) ? cura.z : (j == 2) ? cura.w : nxta.x;
        float xb = (j == 0) ? curb.y : (j == 1) ? curb.z : (j == 2) ? curb.w : nxtb.x;

        float s1a = xa + fmaxf((d[0] + e[0]) + (f[0] + gg[0]), 0.f);
        float s2a = s1a + fmaxf((d[1] + e[1]) + (f[1] + gg[1]), 0.f);
        float s1b = xb + fmaxf((d[2] + e[2]) + (f[2] + gg[2]), 0.f);
        float s2b = s1b + fmaxf((d[3] + e[3]) + (f[3] + gg[3]), 0.f);

        // B st.asyncs to all 4 CTAs first (they gate everyone's next step),
        // then the fire-and-forget u-partial STG.
        if (w < WW - 1) {
            const uint32_t barOff = (uint32_t)wb * 8u;
            const uint32_t bufOff = (uint32_t)wb * (CC * 8 * 2);
            __half2 v0h = __floats2half2_rn(s1a, s2a);
            __half2 v1h = __floats2half2_rn(s1b, s2b);
            uint32_t v0 = *reinterpret_cast<uint32_t*>(&v0h);
            uint32_t v1 = *reinterpret_cast<uint32_t*>(&v1h);
#pragma unroll
            for (int r = 0; r < CLW; r++) {
                ST_ASYNC_U32(bAll[r] + bufOff + bo0, v0, barAll[r] + barOff);
                ST_ASYNC_U32(bAll[r] + bufOff + bo1, v1, barAll[r] + barOff);
            }
        }
        gpart[(size_t)w * (NBLK * 128)] = w1a * s2a + w1b * s2b;

        if (j == 3) { cura = nxta; curb = nxtb; }
    }

    CLUSTER_SYNC();
}

// ===========================================================================
// Reduce u: g_u[col][127-w] = sum over (rank, wid, g, ch) of g_part[w][blk][tid].
// grid = 128 (w), block = 128 (col). Deterministic fixed-order summation.
// For column c: cg = c>>2 (cluster), tg = c&3; contributing threads are
// tid = 4*q + tg (q = wid*8+g, 0..31) in blocks blk = cg*4 + rank.
__global__ void reduce_u_kernel() {
    int w = blockIdx.x;
    int c = threadIdx.x;              // column 0..127
    int tg = c & 3;
    int cg = c >> 2;                  // cluster 0..31
    const float* base = g_part + (size_t)w * (NBLK * 128);
    float s = 0.f;
#pragma unroll
    for (int rank = 0; rank < 4; rank++) {
        const float* pb = base + (cg * 4 + rank) * 128 + tg;
#pragma unroll
        for (int q = 0; q < 32; q++)
            s += pb[q * 4];
    }
    g_u[c * WW + (WW - 1 - w)] = s;
}

// ===========================================================================
__device__ __forceinline__ void stage_rows(float* su0, float* su1,
                                           int b, int i, float& wy) {
    float ys = (float)i * (63.0f / 255.0f);
    int y0 = (int)ys;
    wy = ys - (float)y0;
    int y1 = min(y0 + 1, HH - 1);
    int t = threadIdx.x;
    if (t < 128)      su0[t]       = g_u[(b * HH + y0) * WW + t];
    else if (t < 256) su1[t - 128] = g_u[(b * HH + y1) * WW + (t - 128)];
}

__device__ __forceinline__ float bilin(const float* su0, const float* su1,
                                       int j, float wy) {
    float xs = (float)j * (127.0f / 511.0f);
    int x0 = (int)xs;
    float wx = xs - (float)x0;
    int x1 = min(x0 + 1, WW - 1);
    float r0 = su0[x0] * (1.f - wy) + su1[x0] * wy;
    float r1 = su0[x1] * (1.f - wy) + su1[x1] * wy;
    return r0 * (1.f - wx) + r1 * wx;
}

__global__ void stats_kernel() {
    __shared__ float su0[128], su1[128];
    __shared__ float rs[8], rq[8];
    int row = blockIdx.x;
    int b = row >> 8, i = row & 255;
    float wy;
    stage_rows(su0, su1, b, i, wy);
    __syncthreads();

    int t = threadIdx.x;
    float sum = 0.f, sq = 0.f;
#pragma unroll
    for (int rr = 0; rr < 2; rr++) {
        float v = bilin(su0, su1, t + rr * 256, wy);
        sum += v;
        sq  += v * v;
    }
#pragma unroll
    for (int o = 16; o; o >>= 1) {
        sum += __shfl_xor_sync(0xffffffffu, sum, o);
        sq  += __shfl_xor_sync(0xffffffffu, sq,  o);
    }
    if ((t & 31) == 0) { rs[t >> 5] = sum; rq[t >> 5] = sq; }
    __syncthreads();
    if (t == 0) {
        float a = 0.f, c = 0.f;
#pragma unroll
        for (int k = 0; k < 8; k++) { a += rs[k]; c += rq[k]; }
        g_psum[row] = a; g_psumsq[row] = c;
    }
}

// output kernel with finalize folded in: every block redundantly reduces the
// 512 partial sums (hot in L2), then applies BN + sigmoid to its row.
__global__ void output_kernel(float* __restrict__ out,
                              const float* __restrict__ gamma,
                              const float* __restrict__ beta) {
    __shared__ float su0[128], su1[128];
    __shared__ float rs[8], rq[8];
    __shared__ float stats2[2];
    int row = blockIdx.x;
    int b = row >> 8, i = row & 255;
    float wy;
    stage_rows(su0, su1, b, i, wy);

    int t = threadIdx.x;
    float sum = g_psum[t] + g_psum[t + 256];
    float sq  = g_psumsq[t] + g_psumsq[t + 256];
#pragma unroll
    for (int o = 16; o; o >>= 1) {
        sum += __shfl_xor_sync(0xffffffffu, sum, o);
        sq  += __shfl_xor_sync(0xffffffffu, sq,  o);
    }
    if ((t & 31) == 0) { rs[t >> 5] = sum; rq[t >> 5] = sq; }
    __syncthreads();
    if (t == 0) {
        float a = 0.f, c = 0.f;
#pragma unroll
        for (int k = 0; k < 8; k++) { a += rs[k]; c += rq[k]; }
        float inv_n = 1.0f / (float)NOUT;
        float mean  = a * inv_n;
        float var   = c * inv_n - mean * mean;
        stats2[0] = mean;
        stats2[1] = rsqrtf(var + 1e-5f);
    }
    __syncthreads();

    float mean = stats2[0], istd = stats2[1];
    float gm = gamma[0], bt = beta[0];
#pragma unroll
    for (int rr = 0; rr < 2; rr++) {
        int j = t + rr * 256;
        float v = bilin(su0, su1, j, wy);
        float y = (v - mean) * istd * gm + bt;
        out[row * WO + j] = 1.0f / (1.0f + expf(-y));
    }
}

// ===========================================================================
extern "C" void kernel_launch(void* const* d_in, const int* in_sizes, int n_in,
                              void* d_out, int out_size) {
    const float* p2    = (const float*)d_in[0];
    const float* convw = (const float*)d_in[1];
    const float* conv1 = (const float*)d_in[2];
    const float* gamma = (const float*)d_in[3];
    const float* beta  = (const float*)d_in[4];
    float* out = (float*)d_out;

    extract_M_kernel<<<256, 256>>>(convw);
    scnn_hmma_kernel<<<NBLK, 128>>>(p2, conv1);
    reduce_u_kernel<<<WW, 128>>>();
    stats_kernel<<<NROWS, 256>>>();
    output_kernel<<<NROWS, 256>>>(out, gamma, beta);
}